// round 9
// baseline (speedup 1.0000x reference)
#include <cuda_runtime.h>
#include <math.h>
#include <stdint.h>

// Problem constants
#define BB 16          // batch
#define SS 4096        // sequence
#define DD 64          // head dim
#define HH 8           // n_hashes
#define NB 64          // buckets per hash
#define NROT 32        // n_buckets/2 rotation outputs
#define TBK 512        // total buckets per batch (HH*NB)
#define CHUNKS 512     // sorted chunks per batch
#define BSZ 64         // bucket/chunk size
#define KEYS 128       // keys per chunk (own + look-back)
#define TOT (HH*SS)    // 32768 sorted entries per batch

// ---- packed f32x2 helpers: each lane is an exact scalar fp32 fma.
__device__ __forceinline__ uint64_t ffma2(uint64_t a, uint64_t b, uint64_t c) {
    uint64_t d;
    asm("fma.rn.f32x2 %0,%1,%2,%3;" : "=l"(d) : "l"(a), "l"(b), "l"(c));
    return d;
}
__device__ __forceinline__ uint64_t pack2(float x) {
    uint64_t r; uint32_t b = __float_as_uint(x);
    asm("mov.b64 %0,{%1,%1};" : "=l"(r) : "r"(b));
    return r;
}
__device__ __forceinline__ void unpack2(uint64_t p, float& a, float& b) {
    uint32_t lo, hi;
    asm("mov.b64 {%0,%1},%2;" : "=r"(lo), "=r"(hi) : "l"(p));
    a = __uint_as_float(lo); b = __uint_as_float(hi);
}

// ---------------- scratch (device globals; zero-initialized at load) ---------
__device__ int   g_buckets[BB*TOT];
__device__ int   g_hist[BB*TBK];
__device__ int   g_off[BB*TBK];
__device__ int   g_tick[BB*TOT];
__device__ float g_logits[BB*TOT];
__device__ float g_o[(size_t)BB*TOT*DD];     // per-hash outputs, 128 MB

// ---------------- k_zero: re-zero histogram AFTER scan consumed it ----------
__global__ void k_zero() {
    int i = blockIdx.x * blockDim.x + threadIdx.x;
    if (i < BB*TBK) g_hist[i] = 0;
}

// ---------------- kernel 1: LSH hashing (exact sequential chains over f) -----
__global__ void __launch_bounds__(256) k_hash(const float* __restrict__ qk,
                                              const float* __restrict__ rot) {
    extern __shared__ float srot[];          // [D][H][NROT] = 16384 floats
    for (int i = threadIdx.x; i < DD*HH*NROT; i += blockDim.x) srot[i] = rot[i];
    __syncthreads();

    int g = blockIdx.x * blockDim.x + threadIdx.x;  // global token (b*S + t)
    int b = g >> 12;
    int t = g & (SS - 1);

    float q[DD];
    const float4* qp = (const float4*)(qk + (size_t)g * DD);
#pragma unroll
    for (int i = 0; i < 16; i++) {
        float4 x = qp[i];
        q[4*i] = x.x; q[4*i+1] = x.y; q[4*i+2] = x.z; q[4*i+3] = x.w;
    }

    for (int h = 0; h < HH; h++) {
        uint64_t acc[16];
#pragma unroll
        for (int p = 0; p < 16; p++) acc[p] = 0ull;
#pragma unroll 2
        for (int f = 0; f < DD; f++) {
            uint64_t q2 = pack2(q[f]);
            const ulonglong2* rp = (const ulonglong2*)(srot + f*(HH*NROT) + h*NROT);
#pragma unroll
            for (int u = 0; u < 8; u++) {
                ulonglong2 rr = rp[u];                 // broadcast LDS.128
                acc[2*u]   = ffma2(q2, rr.x, acc[2*u]);
                acc[2*u+1] = ffma2(q2, rr.y, acc[2*u+1]);
            }
        }
        float bv = -INFINITY; int bi = 0;
#pragma unroll
        for (int p = 0; p < 16; p++) {
            float d0, d1; unpack2(acc[p], d0, d1);
            int i0 = 2*p;
            if (d0 > bv || (d0 == bv && i0 < bi)) { bv = d0; bi = i0; }
            float n0 = -d0; int m0 = NROT + i0;
            if (n0 > bv || (n0 == bv && m0 < bi)) { bv = n0; bi = m0; }
            int i1 = 2*p + 1;
            if (d1 > bv || (d1 == bv && i1 < bi)) { bv = d1; bi = i1; }
            float n1 = -d1; int m1 = NROT + i1;
            if (n1 > bv || (n1 == bv && m1 < bi)) { bv = n1; bi = m1; }
        }
        int bucket = bi + h * NB;
        g_buckets[b*TOT + h*SS + t] = bucket;
        atomicAdd(&g_hist[b*TBK + bucket], 1);
    }
}

// ---------------- kernel 2: exclusive scan of histogram (per batch) ----------
__global__ void k_scan() {
    __shared__ int s[TBK];
    int b = blockIdx.x, t = threadIdx.x;
    int myv = g_hist[b*TBK + t];
    s[t] = myv;
    __syncthreads();
    for (int o = 1; o < TBK; o <<= 1) {
        int v = (t >= o) ? s[t - o] : 0;
        __syncthreads();
        s[t] += v;
        __syncthreads();
    }
    g_off[b*TBK + t] = s[t] - myv;
}

// ---------------- kernel 3: counting-sort scatter, warp-ballot (stable) ------
__global__ void __launch_bounds__(256) k_scatter() {
    int w = (blockIdx.x * blockDim.x + threadIdx.x) >> 5;  // one warp per bucket
    if (w >= BB*TBK) return;
    int lane = threadIdx.x & 31;
    int b = w / TBK, bucket = w % TBK;
    int h = bucket >> 6;
    const int* bp = g_buckets + b*TOT + h*SS;
    int off = g_off[w];
    int* out = g_tick + b*TOT;
    int base = h * SS;
    for (int t0 = 0; t0 < SS; t0 += 32) {
        int t = t0 + lane;
        bool m = (bp[t] == bucket);
        unsigned msk = __ballot_sync(0xffffffffu, m);
        int pre = __popc(msk & ((1u << lane) - 1));
        if (m) out[off + pre] = base + t;       // ascending t => stable
        off += __popc(msk);
    }
}

// ---------------- kernel 4: chunked attention (big register tiles) -----------
// dots[i,j] = ||q_i|| * (k̂_i · k̂_j) / 8 — queries are rows 0..63 of Ks2.
// Layouts:
//   Ks2 [f=64][j=128]  normalized keys, transposed
//   Vs  [j=128][d=64]  row-major
//   Smt [j=128][i=68-stride]  scores transposed (i contiguous)
#define KSTR2 128
#define VSTR2 64
#define SMTSTR 68
#define KS2_SZ (DD*KSTR2)
#define VS_SZ  (KEYS*VSTR2)
#define SMT_SZ (KEYS*SMTSTR)
#define ATT_SMEM ((KS2_SZ + VS_SZ + SMT_SZ + BSZ)*4 + KEYS*4 + BSZ*4)

__global__ void __launch_bounds__(512, 2) k_attn(const float* __restrict__ qk,
                                                 const float* __restrict__ v) {
    extern __shared__ char smraw[];
    float* Ks2   = (float*)smraw;
    float* Vs    = Ks2 + KS2_SZ;
    float* Smt   = Vs + VS_SZ;
    float* norms = Smt + SMT_SZ;                  // query norms (64)
    int*   tkt   = (int*)(norms + BSZ);           // key positions (t)
    int*   qtk   = tkt + KEYS;                    // query tickers (h*S+t)

    int c = blockIdx.x, b = blockIdx.y;
    int tid = threadIdx.x;

    // ---- load: 512 threads, each owns half of one row (128B).
    //      rows 0..127 = K (rows 0..63 also queries), rows 128..255 = V.
    {
        int r    = tid >> 1;                      // 0..255
        int half = tid & 1;                       // which 32-float half
        int kr   = r & 127;
        int src_chunk = (kr < BSZ) ? c : (c == 0 ? CHUNKS - 1 : c - 1);
        int pos = kr & (BSZ - 1);
        int ticker = g_tick[b*TOT + src_chunk*BSZ + pos];
        int t = ticker & (SS - 1);

        if (r < 128) {
            if (half == 0) {
                tkt[kr] = t;
                if (kr < BSZ) qtk[kr] = ticker;
            }
            float row[32];
            const float4* kp = (const float4*)(qk + ((size_t)b*SS + t) * DD + half*32);
#pragma unroll
            for (int i = 0; i < 8; i++) {
                float4 x = kp[i];
                row[4*i] = x.x; row[4*i+1] = x.y; row[4*i+2] = x.z; row[4*i+3] = x.w;
            }
            float ssq = 0.f;
#pragma unroll
            for (int f = 0; f < 32; f++) ssq = fmaf(row[f], row[f], ssq);
            float oth = __shfl_xor_sync(0xffffffffu, ssq, 1);
            float lo = half ? oth : ssq, hi = half ? ssq : oth;
            float nrm = sqrtf(lo + hi);           // identical in both half-threads
            float inv = 1.0f / fmaxf(nrm, 1e-12f);
#pragma unroll
            for (int f = 0; f < 32; f++) Ks2[(half*32 + f)*KSTR2 + kr] = row[f] * inv;
            if (kr < BSZ && half == 0) norms[kr] = nrm;
        } else {
            const float4* vp = (const float4*)(v + ((size_t)b*SS + t) * DD + half*32);
            float* vd = Vs + kr*VSTR2 + half*32;
#pragma unroll
            for (int i = 0; i < 8; i++) {
                float4 x = vp[i];
                vd[4*i] = x.x; vd[4*i+1] = x.y; vd[4*i+2] = x.z; vd[4*i+3] = x.w;
            }
        }
    }
    __syncthreads();

    // ---- phase 1: dots, 8i x 4j register tile on 256 threads (1.5 B/MAC). --
    if (tid < 256) {
        int it = tid & 7;                         // 8 i-tiles of 8
        int jt = tid >> 3;                        // 32 j-tiles of 4
        int i0 = it * 8, j0 = jt * 4;
        uint64_t acc[4][4];                       // [i-pair][j]
#pragma unroll
        for (int p = 0; p < 4; p++)
#pragma unroll
            for (int u = 0; u < 4; u++) acc[p][u] = 0ull;
        for (int f = 0; f < DD; f++) {
            const float* krow = Ks2 + f*KSTR2;
            ulonglong2 qa = *(const ulonglong2*)(krow + i0);       // i0..i0+3
            ulonglong2 qb = *(const ulonglong2*)(krow + i0 + 4);   // i0+4..i0+7
            float4 kk = *(const float4*)(krow + j0);
            uint64_t k0 = pack2(kk.x), k1 = pack2(kk.y);
            uint64_t k2 = pack2(kk.z), k3 = pack2(kk.w);
            acc[0][0] = ffma2(qa.x, k0, acc[0][0]);
            acc[1][0] = ffma2(qa.y, k0, acc[1][0]);
            acc[2][0] = ffma2(qb.x, k0, acc[2][0]);
            acc[3][0] = ffma2(qb.y, k0, acc[3][0]);
            acc[0][1] = ffma2(qa.x, k1, acc[0][1]);
            acc[1][1] = ffma2(qa.y, k1, acc[1][1]);
            acc[2][1] = ffma2(qb.x, k1, acc[2][1]);
            acc[3][1] = ffma2(qb.y, k1, acc[3][1]);
            acc[0][2] = ffma2(qa.x, k2, acc[0][2]);
            acc[1][2] = ffma2(qa.y, k2, acc[1][2]);
            acc[2][2] = ffma2(qb.x, k2, acc[2][2]);
            acc[3][2] = ffma2(qb.y, k2, acc[3][2]);
            acc[0][3] = ffma2(qa.x, k3, acc[0][3]);
            acc[1][3] = ffma2(qa.y, k3, acc[1][3]);
            acc[2][3] = ffma2(qb.x, k3, acc[2][3]);
            acc[3][3] = ffma2(qb.y, k3, acc[3][3]);
        }
        float sc[8]; int tki[8];
#pragma unroll
        for (int u = 0; u < 8; u++) {
            tki[u] = tkt[i0+u];
            sc[u] = norms[i0+u] * 0.125f;
        }
#pragma unroll
        for (int u = 0; u < 4; u++) {
            int j = j0 + u;
            int tj = tkt[j];
            float d[8];
            unpack2(acc[0][u], d[0], d[1]);
            unpack2(acc[1][u], d[2], d[3]);
            unpack2(acc[2][u], d[4], d[5]);
            unpack2(acc[3][u], d[6], d[7]);
            float4 x0, x1;
            x0.x = (tki[0] == tj) ? -1e5f : d[0]*sc[0];
            x0.y = (tki[1] == tj) ? -1e5f : d[1]*sc[1];
            x0.z = (tki[2] == tj) ? -1e5f : d[2]*sc[2];
            x0.w = (tki[3] == tj) ? -1e5f : d[3]*sc[3];
            x1.x = (tki[4] == tj) ? -1e5f : d[4]*sc[4];
            x1.y = (tki[5] == tj) ? -1e5f : d[5]*sc[5];
            x1.z = (tki[6] == tj) ? -1e5f : d[6]*sc[6];
            x1.w = (tki[7] == tj) ? -1e5f : d[7]*sc[7];
            *(float4*)(Smt + j*SMTSTR + i0)     = x0;
            *(float4*)(Smt + j*SMTSTR + i0 + 4) = x1;
        }
    }
    __syncthreads();

    // ---- phase 2: softmax over j per row i; 8 lanes/row, j interleaved. ----
    {
        int i  = tid >> 3;
        int cq = tid & 7;
        float m = -INFINITY;
#pragma unroll
        for (int jj = 0; jj < 16; jj++)
            m = fmaxf(m, Smt[(cq + 8*jj)*SMTSTR + i]);
        m = fmaxf(m, __shfl_xor_sync(0xffffffffu, m, 1));
        m = fmaxf(m, __shfl_xor_sync(0xffffffffu, m, 2));
        m = fmaxf(m, __shfl_xor_sync(0xffffffffu, m, 4));
        float s = 0.f;
#pragma unroll
        for (int jj = 0; jj < 16; jj++)
            s += expf(Smt[(cq + 8*jj)*SMTSTR + i] - m);
        s += __shfl_xor_sync(0xffffffffu, s, 1);
        s += __shfl_xor_sync(0xffffffffu, s, 2);
        s += __shfl_xor_sync(0xffffffffu, s, 4);
        float lse = m + logf(s);
#pragma unroll
        for (int jj = 0; jj < 16; jj++) {
            float* p = Smt + (cq + 8*jj)*SMTSTR + i;
            *p = expf(*p - lse);
        }
        if (cq == 0) g_logits[b*TOT + qtk[i]] = lse;
    }
    __syncthreads();

    // ---- phase 3: PV, 4i x 8d tile on 128 threads (1.5 B/MAC); V pairs
    //      load directly as u64 (pair over d, no pack for V). ----
    if (tid < 128) {
        int ig = tid & 15;                        // 16 i-groups of 4
        int dg = tid >> 4;                        // 8 d-groups of 8
        int i0 = ig * 4, d0 = dg * 8;
        uint64_t acc[4][4];                       // [i][d-pair]
#pragma unroll
        for (int p = 0; p < 4; p++)
#pragma unroll
            for (int u = 0; u < 4; u++) acc[p][u] = 0ull;
        for (int j = 0; j < KEYS; j++) {
            float4 pp = *(const float4*)(Smt + j*SMTSTR + i0);
            ulonglong2 va = *(const ulonglong2*)(Vs + j*VSTR2 + d0);
            ulonglong2 vb = *(const ulonglong2*)(Vs + j*VSTR2 + d0 + 4);
            uint64_t p0 = pack2(pp.x), p1 = pack2(pp.y);
            uint64_t p2 = pack2(pp.z), p3 = pack2(pp.w);
            acc[0][0] = ffma2(p0, va.x, acc[0][0]);
            acc[0][1] = ffma2(p0, va.y, acc[0][1]);
            acc[0][2] = ffma2(p0, vb.x, acc[0][2]);
            acc[0][3] = ffma2(p0, vb.y, acc[0][3]);
            acc[1][0] = ffma2(p1, va.x, acc[1][0]);
            acc[1][1] = ffma2(p1, va.y, acc[1][1]);
            acc[1][2] = ffma2(p1, vb.x, acc[1][2]);
            acc[1][3] = ffma2(p1, vb.y, acc[1][3]);
            acc[2][0] = ffma2(p2, va.x, acc[2][0]);
            acc[2][1] = ffma2(p2, va.y, acc[2][1]);
            acc[2][2] = ffma2(p2, vb.x, acc[2][2]);
            acc[2][3] = ffma2(p2, vb.y, acc[2][3]);
            acc[3][0] = ffma2(p3, va.x, acc[3][0]);
            acc[3][1] = ffma2(p3, va.y, acc[3][1]);
            acc[3][2] = ffma2(p3, vb.x, acc[3][2]);
            acc[3][3] = ffma2(p3, vb.y, acc[3][3]);
        }
#pragma unroll
        for (int u = 0; u < 4; u++) {
            float o[8];
            unpack2(acc[u][0], o[0], o[1]);
            unpack2(acc[u][1], o[2], o[3]);
            unpack2(acc[u][2], o[4], o[5]);
            unpack2(acc[u][3], o[6], o[7]);
            float* op = g_o + ((size_t)b*TOT + qtk[i0+u]) * DD + d0;
            float4 x0 = {o[0], o[1], o[2], o[3]};
            float4 x1 = {o[4], o[5], o[6], o[7]};
            *(float4*)(op)     = x0;
            *(float4*)(op + 4) = x1;
        }
    }
}

// ---------------- kernel 5: combine hash rounds (elementwise, fp32) ----------
__global__ void k_combine(float* __restrict__ out) {
    int idx = blockIdx.x * blockDim.x + threadIdx.x;  // over B*S*16 (float4 lanes)
    if (idx >= BB*SS*16) return;
    int q  = idx & 15;
    int bt = idx >> 4;            // b*S + t
    int b  = bt >> 12, t = bt & (SS - 1);

    const float* lp = g_logits + b*TOT + t;
    float l[HH];
    float m = -INFINITY;
#pragma unroll
    for (int h = 0; h < HH; h++) { l[h] = lp[h*SS]; m = fmaxf(m, l[h]); }
    float s = 0.f;
#pragma unroll
    for (int h = 0; h < HH; h++) { l[h] = expf(l[h] - m); s += l[h]; }
    float invs = 1.0f / s;

    float4 acc = {0.f, 0.f, 0.f, 0.f};
#pragma unroll
    for (int h = 0; h < HH; h++) {
        const float4* op = (const float4*)(g_o + ((size_t)b*TOT + h*SS + t) * DD) + q;
        float4 x = *op;
        float w = l[h] * invs;
        acc.x = fmaf(w, x.x, acc.x);
        acc.y = fmaf(w, x.y, acc.y);
        acc.z = fmaf(w, x.z, acc.z);
        acc.w = fmaf(w, x.w, acc.w);
    }
    ((float4*)out)[(size_t)bt * 16 + q] = acc;
}

// ---------------- kernel 6: buckets output (2nd tuple element) ---------------
__global__ void k_buckets(float* __restrict__ out) {
    int i = blockIdx.x * blockDim.x + threadIdx.x;
    if (i < BB*TOT) out[i] = (float)g_buckets[i];
}

// ---------------- launcher ---------------------------------------------------
// k_attn stays 4th (the slot ncu profiles). g_hist starts zeroed (static init)
// and k_zero re-zeroes it after k_scan reads it -> identical state every call.
extern "C" void kernel_launch(void* const* d_in, const int* in_sizes, int n_in,
                              void* d_out, int out_size) {
    const float* qk  = (const float*)d_in[0];
    const float* v   = (const float*)d_in[1];
    const float* rot = (const float*)d_in[2];
    float* out = (float*)d_out;

    cudaFuncSetAttribute(k_hash, cudaFuncAttributeMaxDynamicSharedMemorySize,
                         DD*HH*NROT*4);
    cudaFuncSetAttribute(k_attn, cudaFuncAttributeMaxDynamicSharedMemorySize,
                         ATT_SMEM);

    k_hash<<<BB*SS / 256, 256, DD*HH*NROT*4>>>(qk, rot);
    k_scan<<<BB, TBK>>>();
    k_scatter<<<(BB*TBK*32 + 255) / 256, 256>>>();
    dim3 ag(CHUNKS, BB);
    k_attn<<<ag, 512, ATT_SMEM>>>(qk, v);
    k_zero<<<(BB*TBK + 255) / 256, 256>>>();
    k_combine<<<(BB*SS*16 + 255) / 256, 256>>>(out);
    if (out_size >= BB*SS*DD + BB*TOT) {
        k_buckets<<<(BB*TOT + 255) / 256, 256>>>(out + (size_t)BB*SS*DD);
    }
}

// round 10
// speedup vs baseline: 1.0572x; 1.0572x over previous
#include <cuda_runtime.h>
#include <math.h>
#include <stdint.h>

// Problem constants
#define BB 16          // batch
#define SS 4096        // sequence
#define DD 64          // head dim
#define HH 8           // n_hashes
#define NB 64          // buckets per hash
#define NROT 32        // n_buckets/2 rotation outputs
#define TBK 512        // total buckets per batch (HH*NB)
#define CHUNKS 512     // sorted chunks per batch
#define BSZ 64         // bucket/chunk size
#define KEYS 128       // keys per chunk (own + look-back)
#define TOT (HH*SS)    // 32768 sorted entries per batch

// ---- packed f32x2 helpers: each lane is an exact scalar fp32 fma.
__device__ __forceinline__ uint64_t ffma2(uint64_t a, uint64_t b, uint64_t c) {
    uint64_t d;
    asm("fma.rn.f32x2 %0,%1,%2,%3;" : "=l"(d) : "l"(a), "l"(b), "l"(c));
    return d;
}
__device__ __forceinline__ uint64_t pack2(float x) {
    uint64_t r; uint32_t b = __float_as_uint(x);
    asm("mov.b64 %0,{%1,%1};" : "=l"(r) : "r"(b));
    return r;
}
__device__ __forceinline__ void unpack2(uint64_t p, float& a, float& b) {
    uint32_t lo, hi;
    asm("mov.b64 {%0,%1},%2;" : "=r"(lo), "=r"(hi) : "l"(p));
    a = __uint_as_float(lo); b = __uint_as_float(hi);
}

// ---------------- scratch (device globals; zero-initialized at load) ---------
__device__ int   g_buckets[BB*TOT];
__device__ int   g_hist[BB*TBK];
__device__ int   g_off[BB*TBK];
__device__ int   g_tick[BB*TOT];
__device__ float g_logits[BB*TOT];
__device__ float g_o[(size_t)BB*TOT*DD];     // per-hash outputs, 128 MB

// ---------------- k_zero: re-zero histogram AFTER scan consumed it ----------
__global__ void k_zero() {
    int i = blockIdx.x * blockDim.x + threadIdx.x;
    if (i < BB*TBK) g_hist[i] = 0;
}

// ---------------- kernel 1: LSH hashing (exact sequential chains over f) -----
__global__ void __launch_bounds__(256) k_hash(const float* __restrict__ qk,
                                              const float* __restrict__ rot) {
    extern __shared__ float srot[];          // [D][H][NROT] = 16384 floats
    for (int i = threadIdx.x; i < DD*HH*NROT; i += blockDim.x) srot[i] = rot[i];
    __syncthreads();

    int g = blockIdx.x * blockDim.x + threadIdx.x;  // global token (b*S + t)
    int b = g >> 12;
    int t = g & (SS - 1);

    float q[DD];
    const float4* qp = (const float4*)(qk + (size_t)g * DD);
#pragma unroll
    for (int i = 0; i < 16; i++) {
        float4 x = qp[i];
        q[4*i] = x.x; q[4*i+1] = x.y; q[4*i+2] = x.z; q[4*i+3] = x.w;
    }

    for (int h = 0; h < HH; h++) {
        uint64_t acc[16];
#pragma unroll
        for (int p = 0; p < 16; p++) acc[p] = 0ull;
#pragma unroll 2
        for (int f = 0; f < DD; f++) {
            uint64_t q2 = pack2(q[f]);
            const ulonglong2* rp = (const ulonglong2*)(srot + f*(HH*NROT) + h*NROT);
#pragma unroll
            for (int u = 0; u < 8; u++) {
                ulonglong2 rr = rp[u];                 // broadcast LDS.128
                acc[2*u]   = ffma2(q2, rr.x, acc[2*u]);
                acc[2*u+1] = ffma2(q2, rr.y, acc[2*u+1]);
            }
        }
        float bv = -INFINITY; int bi = 0;
#pragma unroll
        for (int p = 0; p < 16; p++) {
            float d0, d1; unpack2(acc[p], d0, d1);
            int i0 = 2*p;
            if (d0 > bv || (d0 == bv && i0 < bi)) { bv = d0; bi = i0; }
            float n0 = -d0; int m0 = NROT + i0;
            if (n0 > bv || (n0 == bv && m0 < bi)) { bv = n0; bi = m0; }
            int i1 = 2*p + 1;
            if (d1 > bv || (d1 == bv && i1 < bi)) { bv = d1; bi = i1; }
            float n1 = -d1; int m1 = NROT + i1;
            if (n1 > bv || (n1 == bv && m1 < bi)) { bv = n1; bi = m1; }
        }
        int bucket = bi + h * NB;
        g_buckets[b*TOT + h*SS + t] = bucket;
        atomicAdd(&g_hist[b*TBK + bucket], 1);
    }
}

// ---------------- kernel 2: exclusive scan of histogram (per batch) ----------
__global__ void k_scan() {
    __shared__ int s[TBK];
    int b = blockIdx.x, t = threadIdx.x;
    int myv = g_hist[b*TBK + t];
    s[t] = myv;
    __syncthreads();
    for (int o = 1; o < TBK; o <<= 1) {
        int v = (t >= o) ? s[t - o] : 0;
        __syncthreads();
        s[t] += v;
        __syncthreads();
    }
    g_off[b*TBK + t] = s[t] - myv;
}

// ---------------- kernel 3: counting-sort scatter, warp-ballot, int4 loads ---
__global__ void __launch_bounds__(256) k_scatter() {
    int w = (blockIdx.x * blockDim.x + threadIdx.x) >> 5;  // one warp per bucket
    if (w >= BB*TBK) return;
    int lane = threadIdx.x & 31;
    int b = w / TBK, bucket = w % TBK;
    int h = bucket >> 6;
    const int4* bp = (const int4*)(g_buckets + b*TOT + h*SS);
    int off = g_off[w];
    int* out = g_tick + b*TOT;
    int base = h * SS;
    unsigned lmask = (1u << lane) - 1;
#pragma unroll 2
    for (int t0 = 0; t0 < SS; t0 += 128) {       // 128 t per iter: LDG.128
        int4 vv = bp[(t0 >> 2) + lane];          // lane covers t0+4*lane..+3
        int tb = base + t0 + 4*lane;
        unsigned m0 = __ballot_sync(0xffffffffu, vv.x == bucket);
        unsigned m1 = __ballot_sync(0xffffffffu, vv.y == bucket);
        unsigned m2 = __ballot_sync(0xffffffffu, vv.z == bucket);
        unsigned m3 = __ballot_sync(0xffffffffu, vv.w == bucket);
        // stable order: t = t0 + 4*lane + s  -> sort by (lane, s): for each
        // lane in order, its 4 slots. rank = (#set with lane'<lane over all s)
        //                                    + (#set with lane'==lane, s'<s)
        int c0 = __popc(m0 & lmask), c1 = __popc(m1 & lmask);
        int c2 = __popc(m2 & lmask), c3 = __popc(m3 & lmask);
        int mybit0 = (vv.x == bucket), mybit1 = (vv.y == bucket);
        int mybit2 = (vv.z == bucket), mybit3 = (vv.w == bucket);
        int pre = c0 + c1 + c2 + c3;             // lanes before me, all slots
        if (mybit0) out[off + pre] = tb;
        pre += mybit0;
        if (mybit1) out[off + pre] = tb + 1;
        pre += mybit1;
        if (mybit2) out[off + pre] = tb + 2;
        pre += mybit2;
        if (mybit3) out[off + pre] = tb + 3;
        off += __popc(m0) + __popc(m1) + __popc(m2) + __popc(m3);
    }
}

// ---------------- kernel 4: chunked attention (round-8 structure) ------------
// dots[i,j] = ||q_i|| * (k̂_i · k̂_j) / 8 — queries are rows 0..63 of Ks2.
// Layouts:
//   Ks2 [f=64][j=128]  normalized keys, transposed
//   Vs  [j=128][d=64]  row-major
//   Smt [j=128][i=68-stride]  scores transposed (i-pairs contiguous for PV)
#define KSTR2 128
#define VSTR2 64
#define SMTSTR 68
#define KS2_SZ (DD*KSTR2)
#define VS_SZ  (KEYS*VSTR2)
#define SMT_SZ (KEYS*SMTSTR)
#define ATT_SMEM ((KS2_SZ + VS_SZ + SMT_SZ + BSZ)*4 + KEYS*4 + BSZ*4)

__global__ void __launch_bounds__(512, 2) k_attn(const float* __restrict__ qk,
                                                 const float* __restrict__ v) {
    extern __shared__ char smraw[];
    float* Ks2   = (float*)smraw;
    float* Vs    = Ks2 + KS2_SZ;
    float* Smt   = Vs + VS_SZ;
    float* norms = Smt + SMT_SZ;                  // query norms (64)
    int*   tkt   = (int*)(norms + BSZ);           // key positions (t)
    int*   qtk   = tkt + KEYS;                    // query tickers (h*S+t)

    int c = blockIdx.x, b = blockIdx.y;
    int tid = threadIdx.x;

    // ---- load: 512 threads, each owns half of one row (128B).
    //      rows 0..127 = K (rows 0..63 also queries), rows 128..255 = V.
    {
        int r    = tid >> 1;                      // 0..255
        int half = tid & 1;                       // which 32-float half
        int kr   = r & 127;
        int src_chunk = (kr < BSZ) ? c : (c == 0 ? CHUNKS - 1 : c - 1);
        int pos = kr & (BSZ - 1);
        int ticker = g_tick[b*TOT + src_chunk*BSZ + pos];
        int t = ticker & (SS - 1);

        if (r < 128) {
            if (half == 0) {
                tkt[kr] = t;
                if (kr < BSZ) qtk[kr] = ticker;
            }
            float row[32];
            const float4* kp = (const float4*)(qk + ((size_t)b*SS + t) * DD + half*32);
#pragma unroll
            for (int i = 0; i < 8; i++) {
                float4 x = kp[i];
                row[4*i] = x.x; row[4*i+1] = x.y; row[4*i+2] = x.z; row[4*i+3] = x.w;
            }
            float ssq = 0.f;
#pragma unroll
            for (int f = 0; f < 32; f++) ssq = fmaf(row[f], row[f], ssq);
            float oth = __shfl_xor_sync(0xffffffffu, ssq, 1);
            float lo = half ? oth : ssq, hi = half ? ssq : oth;
            float nrm = sqrtf(lo + hi);           // identical in both half-threads
            float inv = 1.0f / fmaxf(nrm, 1e-12f);
#pragma unroll
            for (int f = 0; f < 32; f++) Ks2[(half*32 + f)*KSTR2 + kr] = row[f] * inv;
            if (kr < BSZ && half == 0) norms[kr] = nrm;
        } else {
            const float4* vp = (const float4*)(v + ((size_t)b*SS + t) * DD + half*32);
            float* vd = Vs + kr*VSTR2 + half*32;
#pragma unroll
            for (int i = 0; i < 8; i++) {
                float4 x = vp[i];
                vd[4*i] = x.x; vd[4*i+1] = x.y; vd[4*i+2] = x.z; vd[4*i+3] = x.w;
            }
        }
    }
    __syncthreads();

    // ---- phase 1: dots, 4x4 register tile (outer product over f on Ks2). ----
    {
        int it = tid & 15;                        // i-tile: i0 = 4*it
        int jt = tid >> 4;                        // j-tile: j0 = 4*jt
        int i0 = it * 4, j0 = jt * 4;
        uint64_t a0[4], a1[4];                    // [j] x (i0,i0+1) / (i0+2,i0+3)
#pragma unroll
        for (int u = 0; u < 4; u++) { a0[u] = 0ull; a1[u] = 0ull; }
#pragma unroll 2
        for (int f = 0; f < DD; f++) {
            const float* krow = Ks2 + f*KSTR2;
            ulonglong2 qq = *(const ulonglong2*)(krow + i0);   // q̂ = k̂ cols 0..63
            float4 kk = *(const float4*)(krow + j0);
            uint64_t k0 = pack2(kk.x), k1 = pack2(kk.y);
            uint64_t k2 = pack2(kk.z), k3 = pack2(kk.w);
            a0[0] = ffma2(qq.x, k0, a0[0]); a1[0] = ffma2(qq.y, k0, a1[0]);
            a0[1] = ffma2(qq.x, k1, a0[1]); a1[1] = ffma2(qq.y, k1, a1[1]);
            a0[2] = ffma2(qq.x, k2, a0[2]); a1[2] = ffma2(qq.y, k2, a1[2]);
            a0[3] = ffma2(qq.x, k3, a0[3]); a1[3] = ffma2(qq.y, k3, a1[3]);
        }
        int tki[4], tkj[4];
        float sc[4];
#pragma unroll
        for (int u = 0; u < 4; u++) {
            tki[u] = tkt[i0+u]; tkj[u] = tkt[j0+u];
            sc[u] = norms[i0+u] * 0.125f;
        }
#pragma unroll
        for (int u = 0; u < 4; u++) {
            float d0, d1, d2, d3;
            unpack2(a0[u], d0, d1);
            unpack2(a1[u], d2, d3);
            int tj = tkj[u];
            float4 x;
            x.x = (tki[0] == tj) ? -1e5f : d0 * sc[0];
            x.y = (tki[1] == tj) ? -1e5f : d1 * sc[1];
            x.z = (tki[2] == tj) ? -1e5f : d2 * sc[2];
            x.w = (tki[3] == tj) ? -1e5f : d3 * sc[3];
            *(float4*)(Smt + (j0+u)*SMTSTR + i0) = x;   // transposed store
        }
    }
    __syncthreads();

    // ---- phase 2: softmax; exp computed ONCE, then scaled by 1/s. ----
    {
        int i  = tid >> 3;
        int cq = tid & 7;
        float m = -INFINITY;
#pragma unroll
        for (int jj = 0; jj < 16; jj++)
            m = fmaxf(m, Smt[(cq + 8*jj)*SMTSTR + i]);
        m = fmaxf(m, __shfl_xor_sync(0xffffffffu, m, 1));
        m = fmaxf(m, __shfl_xor_sync(0xffffffffu, m, 2));
        m = fmaxf(m, __shfl_xor_sync(0xffffffffu, m, 4));
        float e[16];
        float s = 0.f;
#pragma unroll
        for (int jj = 0; jj < 16; jj++) {
            e[jj] = expf(Smt[(cq + 8*jj)*SMTSTR + i] - m);
            s += e[jj];
        }
        s += __shfl_xor_sync(0xffffffffu, s, 1);
        s += __shfl_xor_sync(0xffffffffu, s, 2);
        s += __shfl_xor_sync(0xffffffffu, s, 4);
        float invs = 1.0f / s;
#pragma unroll
        for (int jj = 0; jj < 16; jj++)
            Smt[(cq + 8*jj)*SMTSTR + i] = e[jj] * invs;
        if (cq == 0) g_logits[b*TOT + qtk[i]] = m + logf(s);
    }
    __syncthreads();

    // ---- phase 3: PV; warp = 8 i-pairs x 4 d-quarters (64B+64B per j). ----
    {
        int ip = (tid & 7) | ((tid >> 7) << 3);   // i-pair 0..31
        int dt = (tid >> 3) & 15;                 // d-quarter 0..15
        int i0 = ip * 2, d0 = dt * 4;
        uint64_t a0 = 0ull, a1 = 0ull, a2 = 0ull, a3 = 0ull;
#pragma unroll 4
        for (int j = 0; j < KEYS; j++) {
            uint64_t sp = *(const uint64_t*)(Smt + j*SMTSTR + i0);
            float4 vv = *(const float4*)(Vs + j*VSTR2 + d0);
            a0 = ffma2(sp, pack2(vv.x), a0);
            a1 = ffma2(sp, pack2(vv.y), a1);
            a2 = ffma2(sp, pack2(vv.z), a2);
            a3 = ffma2(sp, pack2(vv.w), a3);
        }
        float o0[4], o1[4];
        unpack2(a0, o0[0], o1[0]); unpack2(a1, o0[1], o1[1]);
        unpack2(a2, o0[2], o1[2]); unpack2(a3, o0[3], o1[3]);
        float4 x0 = {o0[0], o0[1], o0[2], o0[3]};
        float4 x1 = {o1[0], o1[1], o1[2], o1[3]};
        *(float4*)(g_o + ((size_t)b*TOT + qtk[i0])     * DD + d0) = x0;
        *(float4*)(g_o + ((size_t)b*TOT + qtk[i0 + 1]) * DD + d0) = x1;
    }
}

// ---------------- kernel 5: combine hash rounds (elementwise, fp32) ----------
__global__ void k_combine(float* __restrict__ out) {
    int idx = blockIdx.x * blockDim.x + threadIdx.x;  // over B*S*16 (float4 lanes)
    if (idx >= BB*SS*16) return;
    int q  = idx & 15;
    int bt = idx >> 4;            // b*S + t
    int b  = bt >> 12, t = bt & (SS - 1);

    const float* lp = g_logits + b*TOT + t;
    float l[HH];
    float m = -INFINITY;
#pragma unroll
    for (int h = 0; h < HH; h++) { l[h] = lp[h*SS]; m = fmaxf(m, l[h]); }
    float s = 0.f;
#pragma unroll
    for (int h = 0; h < HH; h++) { l[h] = expf(l[h] - m); s += l[h]; }
    float invs = 1.0f / s;

    float4 acc = {0.f, 0.f, 0.f, 0.f};
#pragma unroll
    for (int h = 0; h < HH; h++) {
        const float4* op = (const float4*)(g_o + ((size_t)b*TOT + h*SS + t) * DD) + q;
        float4 x = *op;
        float w = l[h] * invs;
        acc.x = fmaf(w, x.x, acc.x);
        acc.y = fmaf(w, x.y, acc.y);
        acc.z = fmaf(w, x.z, acc.z);
        acc.w = fmaf(w, x.w, acc.w);
    }
    ((float4*)out)[(size_t)bt * 16 + q] = acc;
}

// ---------------- kernel 6: buckets output (2nd tuple element) ---------------
__global__ void k_buckets(float* __restrict__ out) {
    int i = blockIdx.x * blockDim.x + threadIdx.x;
    if (i < BB*TOT) out[i] = (float)g_buckets[i];
}

// ---------------- launcher ---------------------------------------------------
// k_attn stays 4th (the slot ncu profiles). g_hist starts zeroed (static init)
// and k_zero re-zeroes it after k_scan reads it -> identical state every call.
extern "C" void kernel_launch(void* const* d_in, const int* in_sizes, int n_in,
                              void* d_out, int out_size) {
    const float* qk  = (const float*)d_in[0];
    const float* v   = (const float*)d_in[1];
    const float* rot = (const float*)d_in[2];
    float* out = (float*)d_out;

    cudaFuncSetAttribute(k_hash, cudaFuncAttributeMaxDynamicSharedMemorySize,
                         DD*HH*NROT*4);
    cudaFuncSetAttribute(k_attn, cudaFuncAttributeMaxDynamicSharedMemorySize,
                         ATT_SMEM);

    k_hash<<<BB*SS / 256, 256, DD*HH*NROT*4>>>(qk, rot);
    k_scan<<<BB, TBK>>>();
    k_scatter<<<(BB*TBK*32 + 255) / 256, 256>>>();
    dim3 ag(CHUNKS, BB);
    k_attn<<<ag, 512, ATT_SMEM>>>(qk, v);
    k_zero<<<(BB*TBK + 255) / 256, 256>>>();
    k_combine<<<(BB*SS*16 + 255) / 256, 256>>>(out);
    if (out_size >= BB*SS*DD + BB*TOT) {
        k_buckets<<<(BB*TOT + 255) / 256, 256>>>(out + (size_t)BB*SS*DD);
    }
}